// round 13
// baseline (speedup 1.0000x reference)
#include <cuda_runtime.h>
#include <cuda_fp16.h>
#include <cstdint>
#include <math.h>

#define BB 64
#define LL 64
#define EE 256
#define MAXN 8192
#define MAXM 8192
#define HASHSZ 8192
#define NEG_INF (__int_as_float(0xff800000))

// ----------------- device-global state (no runtime allocation) -----------------
__device__ float g_feats[MAXN * EE];            // node features (fp32)
__device__ float g_norm[MAXN];                  // node norms (tokens + composed)
__device__ float g_outs[MAXM * EE];             // composed context vectors (fp32)
__device__ __half g_Ahi[MAXM * EE];             // fp16 hi/lo split of g_outs
__device__ __half g_Alo[MAXM * EE];
__device__ __half g_Bhi[MAXN * EE];             // fp16 hi/lo split of g_feats
__device__ __half g_Blo[MAXN * EE];
__device__ float g_pmax[(size_t)MAXM * 64];     // per (row, n-tile) LSE partials
__device__ float g_psum[(size_t)MAXM * 64];
__device__ int   g_rank[30720];
__device__ int   g_tokens[MAXN];
__device__ int   g_index[BB * LL];
__device__ float g_cos[BB * LL];
__device__ int   g_hkey[HASHSZ];
__device__ int   g_hval[HASHSZ];
__device__ int   g_targets[MAXM * 3];
__device__ int   g_M;
__device__ int   g_nodeCount;
__device__ int   g_cnt;
__device__ float g_rowloss[MAXM];

__device__ __forceinline__ float sigmoidf_(float x) { return 1.f / (1.f + expf(-x)); }

__device__ __forceinline__ float warp_dot(const float* a, const float* b) {
    int lane = threadIdx.x & 31;
    float s = 0.f;
#pragma unroll
    for (int k = 0; k < 8; k++) { int e = lane + 32 * k; s += a[e] * b[e]; }
#pragma unroll
    for (int o = 16; o; o >>= 1) s += __shfl_xor_sync(0xffffffffu, s, o);
    return s;
}

// ----------------- setup kernels -----------------
__global__ void k_zero() {
    int i = blockIdx.x * blockDim.x + threadIdx.x;
    if (i < 30720) g_rank[i] = 0;
    if (i < HASHSZ) { g_hkey[i] = -1; g_hval[i] = -1; }
    if (i == 0) { g_M = 0; }
}

__global__ void k_mark(const int* __restrict__ x) {
    int i = blockIdx.x * blockDim.x + threadIdx.x;
    if (i < BB * LL) g_rank[x[i]] = 1;
}

__global__ __launch_bounds__(1024) void k_rank(int NV) {
    __shared__ int scan[1024];
    int tid = threadIdx.x;
    const int CH2 = 30;
    int base = tid * CH2;
    unsigned mask = 0;
    for (int i = 0; i < CH2; i++) {
        int v = base + i;
        if (v < NV && g_rank[v]) mask |= (1u << i);
    }
    int cnt = __popc(mask);
    scan[tid] = cnt;
    __syncthreads();
    for (int o = 1; o < 1024; o <<= 1) {
        int add = (tid >= o) ? scan[tid - o] : 0;
        __syncthreads();
        scan[tid] += add;
        __syncthreads();
    }
    int run = scan[tid] - cnt;
    for (int i = 0; i < CH2; i++) {
        int v = base + i;
        if (v < NV) {
            if (mask & (1u << i)) { g_rank[v] = run; g_tokens[run] = v; run++; }
            else g_rank[v] = -1;
        }
    }
    if (tid == 1023) { g_nodeCount = scan[1023] - 1; g_cnt = scan[1023] - 1; }
}

__global__ void k_init_index(const int* __restrict__ x, int NV) {
    int i = blockIdx.x * blockDim.x + threadIdx.x;
    if (i < BB * LL) {
        int v = x[i];
        g_index[i] = (v == NV - 1) ? -1 : g_rank[v];
    }
}

__global__ void k_init_nodes(const float* __restrict__ emb) {
    int i = blockIdx.x;
    if (i >= g_nodeCount) return;
    int e = threadIdx.x;
    float v = emb[(size_t)g_tokens[i] * EE + e];
    g_feats[i * EE + e] = v;
    float s = v * v;
#pragma unroll
    for (int o = 16; o; o >>= 1) s += __shfl_xor_sync(0xffffffffu, s, o);
    __shared__ float red[8];
    if ((e & 31) == 0) red[e >> 5] = s;
    __syncthreads();
    if (e == 0) {
        float t = 0.f;
#pragma unroll
        for (int w = 0; w < 8; w++) t += red[w];
        g_norm[i] = sqrtf(t);
    }
}

__global__ void k_init_cos() {
    int gw = blockIdx.x * 8 + (threadIdx.x >> 5);
    if (gw >= BB * (LL - 1)) return;
    int r = gw / (LL - 1), j = gw % (LL - 1);
    int iR = g_index[r * LL + j + 1];
    float c;
    if (iR < 0) c = NEG_INF;
    else {
        int iL = g_index[r * LL + j];
        float d = warp_dot(&g_feats[iL * EE], &g_feats[iR * EE]);
        c = d / fmaxf(g_norm[iL] * g_norm[iR], 1e-8f);
    }
    if ((threadIdx.x & 31) == 0) g_cos[r * LL + j] = c;
}

// ----------------- async merge tree: 2 CTAs x 32 warps = one warp per row -----------------
__global__ __launch_bounds__(1024) void k_tree(const float* __restrict__ comp_l,
                                               const float* __restrict__ comp_r,
                                               const float* __restrict__ cb) {
    __shared__ int   s_rIdx[32 * 66];
    __shared__ float s_rCos[32 * 64];
    __shared__ int s_len[64], s_base[64];

    int tid = threadIdx.x, lane = tid & 31, w = tid >> 5;
    int cta = blockIdx.x;
    int r = cta * 32 + w;             // this warp's row
    float slv = sigmoidf_(comp_l[lane & 15]);
    float srv = sigmoidf_(comp_r[lane & 15]);
    float cbv = cb[lane & 15];

    // lens for ALL rows (deterministic target bases, computed per-CTA)
    if (tid < 64) {
        int cnt = 0;
        for (int j = 0; j < 64; j++) cnt += (g_index[tid * 64 + j] != -1);
        s_len[tid] = cnt;
    }
    __syncthreads();
    if (tid == 0) {
        int acc = 0;
        for (int q = 0; q < 64; q++) { s_base[q] = acc; acc += 2 * (s_len[q] - 1); }
        if (cta == 0) g_M = acc;
    }
    // load this CTA's 32 rows
    {
        int i0 = g_index[r * 64 + lane];
        int i1 = g_index[r * 64 + lane + 32];
        s_rIdx[w * 66 + lane] = i0;
        s_rIdx[w * 66 + lane + 32] = i1;
        s_rCos[w * 64 + lane] = g_cos[r * 64 + lane];
        if (lane <= 30) s_rCos[w * 64 + lane + 32] = g_cos[r * 64 + lane + 32];
    }
    __syncthreads();

    int* rIdx = &s_rIdx[w * 66];
    float* rCos = &s_rCos[w * 64];
    int L = s_len[r];
    int tb0 = s_base[r];

    for (int v = L; v >= 2; --v) {
        // argmax over rCos[0..v-2], first-index tiebreak
        float c0 = (lane <= v - 2) ? rCos[lane] : NEG_INF;
        float c1 = (lane + 32 <= v - 2) ? rCos[lane + 32] : NEG_INF;
        float bv; int bi;
        if (c0 >= c1) { bv = c0; bi = lane; } else { bv = c1; bi = lane + 32; }
#pragma unroll
        for (int o = 16; o; o >>= 1) {
            float ov = __shfl_xor_sync(0xffffffffu, bv, o);
            int   oi = __shfl_xor_sync(0xffffffffu, bi, o);
            if (ov > bv || (ov == bv && oi < bi)) { bv = ov; bi = oi; }
        }
        int ms = bi;
        int l = rIdx[ms], rr = rIdx[ms + 1];
        unsigned key = ((unsigned)l << 13) | (unsigned)rr;

        // dedup via GLOBAL hash: lane 0 probes/claims
        int nid = -1, claim = 0; unsigned hh = 0;
        if (lane == 0) {
            unsigned h = (key * 2654435761u) & (HASHSZ - 1);
            for (int p = 0; p < HASHSZ; p++) {
                int old = atomicCAS(&g_hkey[h], -1, (int)key);
                if (old == -1) {
                    claim = 1;
                    nid = atomicAdd(&g_cnt, 1);
                    if (nid >= MAXN) nid = MAXN - 1;  // fail-soft
                    hh = h;
                    break;
                }
                if ((unsigned)old == key) {
                    volatile int* vp = &g_hval[h];
                    int x, t = 0;
                    while ((x = *vp) < 0 && ++t < (1 << 20)) {}
                    nid = (x < 0) ? 0 : x;  // fail-soft
                    break;
                }
                h = (h + 1) & (HASHSZ - 1);
            }
            if (nid < 0) nid = 0;  // fail-soft
        }
        nid   = __shfl_sync(0xffffffffu, nid, 0);
        claim = __shfl_sync(0xffffffffu, claim, 0);
        hh    = __shfl_sync(0xffffffffu, hh, 0);

        float nf[8]; float nn;
        if (claim) {
            const float* FL = &g_feats[(size_t)l * EE];
            const float* FR = &g_feats[(size_t)rr * EE];
            float ss = 0.f;
#pragma unroll
            for (int k = 0; k < 8; k++) {
                float x = FL[lane + 32 * k] * slv + FR[lane + 32 * k] * srv + cbv;
                nf[k] = x;
                g_feats[(size_t)nid * EE + lane + 32 * k] = x;
                ss += x * x;
            }
#pragma unroll
            for (int o = 16; o; o >>= 1) ss += __shfl_xor_sync(0xffffffffu, ss, o);
            nn = sqrtf(ss);
            if (lane == 0) g_norm[nid] = nn;
            __threadfence();                          // feats+norm visible device-wide
            if (lane == 0) *(volatile int*)&g_hval[hh] = nid;  // publish
        } else {
            __threadfence();                          // acquire after spin saw nid
            const float* FN = &g_feats[(size_t)nid * EE];
#pragma unroll
            for (int k = 0; k < 8; k++) nf[k] = FN[lane + 32 * k];
            nn = *(volatile float*)&g_norm[nid];
        }

        // record targets at deterministic per-row offset
        if (lane == 0) {
            int ls = (ms == 0) ? -1 : rIdx[ms - 1];
            int rs = (ms + 2 >= v) ? ((L == 64) ? -2 : -1) : rIdx[ms + 2];
            int tb = tb0 + 2 * (L - v);
            g_targets[tb * 3 + 0] = l;  g_targets[tb * 3 + 1] = ls; g_targets[tb * 3 + 2] = rr;
            g_targets[tb * 3 + 3] = rr; g_targets[tb * 3 + 4] = l;  g_targets[tb * 3 + 5] = rs;
        }

        // shift arrays left past ms (read-before-write within warp)
        int j0 = lane, j1 = lane + 32;
        int ni0 = 0, ni1 = 0; float nc0 = 0.f, nc1 = 0.f;
        if (j0 <= v - 2) ni0 = (j0 == ms) ? nid : rIdx[j0 + (j0 > ms)];
        if (j1 <= v - 2) ni1 = (j1 == ms) ? nid : rIdx[j1 + (j1 > ms)];
        if (j0 <= v - 3) nc0 = (j0 < ms - 1) ? rCos[j0] : ((j0 > ms) ? rCos[j0 + 1] : 0.f);
        if (j1 <= v - 3) nc1 = (j1 < ms - 1) ? rCos[j1] : ((j1 > ms) ? rCos[j1 + 1] : 0.f);
        __syncwarp();
        if (j0 <= v - 2) rIdx[j0] = ni0;
        if (j1 <= v - 2) rIdx[j1] = ni1;
        if (j0 <= v - 3) rCos[j0] = nc0;
        if (j1 <= v - 3) rCos[j1] = nc1;
        __syncwarp();

        // recompute the <=2 affected cosines using reg-resident new feats
        if (ms >= 1) {
            int a = rIdx[ms - 1];
            const float* FA = &g_feats[(size_t)a * EE];
            float s = 0.f;
#pragma unroll
            for (int k = 0; k < 8; k++) s += nf[k] * FA[lane + 32 * k];
#pragma unroll
            for (int o = 16; o; o >>= 1) s += __shfl_xor_sync(0xffffffffu, s, o);
            float c = s / fmaxf(g_norm[a] * nn, 1e-8f);
            if (lane == 0) rCos[ms - 1] = c;
        }
        if (ms <= v - 3) {
            int b = rIdx[ms + 1];
            const float* FB = &g_feats[(size_t)b * EE];
            float s = 0.f;
#pragma unroll
            for (int k = 0; k < 8; k++) s += nf[k] * FB[lane + 32 * k];
#pragma unroll
            for (int o = 16; o; o >>= 1) s += __shfl_xor_sync(0xffffffffu, s, o);
            float c = s / fmaxf(nn * g_norm[b], 1e-8f);
            if (lane == 0) rCos[ms] = c;
        }
        __syncwarp();
    }
}

// append eos (N-2) and sos (N-1); finalize node count from global counter
__global__ void k_finalize(const float* __restrict__ sos, const float* __restrict__ eos) {
    int nc = g_cnt;
    int e = threadIdx.x;
    if (blockIdx.x == 0) {
        g_feats[nc * EE + e] = eos[e];
        if (e == 0) g_nodeCount = nc;
    } else {
        g_feats[(nc + 1) * EE + e] = sos[e];
    }
}

// compose contexts + fp16 hi/lo split in one pass
__global__ void k_outs(const float* __restrict__ comp_l, const float* __restrict__ comp_r,
                       const float* __restrict__ cb) {
    int m = blockIdx.x;
    if (m >= g_M) return;
    int N = g_nodeCount + 2;
    int e = threadIdx.x;
    int t1 = g_targets[m * 3 + 1]; if (t1 < 0) t1 += N;
    int t2 = g_targets[m * 3 + 2]; if (t2 < 0) t2 += N;
    int c = e & 15;
    float sl = sigmoidf_(comp_l[c]), sr = sigmoidf_(comp_r[c]);
    float o = g_feats[t1 * EE + e] * sl + g_feats[t2 * EE + e] * sr + cb[c];
    g_outs[m * EE + e] = o;
    __half h = __float2half_rn(o);
    g_Ahi[m * EE + e] = h;
    g_Alo[m * EE + e] = __float2half_rn(o - __half2float(h));
}

__global__ __launch_bounds__(256) void k_cvtB() {
    int i = blockIdx.x * 256 + threadIdx.x;
    float v = g_feats[i];
    __half h = __float2half_rn(v);
    g_Bhi[i] = h;
    g_Blo[i] = __float2half_rn(v - __half2float(h));
}

// ----------------- mma.sync GEMM with fused partial-LSE epilogue (no logits) -----------------
__device__ __forceinline__ uint32_t smem_u32(const void* p) {
    uint32_t a;
    asm("{ .reg .u64 t; cvta.to.shared.u64 t, %1; cvt.u32.u64 %0, t; }" : "=r"(a) : "l"(p));
    return a;
}
__device__ __forceinline__ void ldsm_x4(uint32_t* r, uint32_t addr) {
    asm volatile("ldmatrix.sync.aligned.m8n8.x4.shared.b16 {%0,%1,%2,%3}, [%4];"
                 : "=r"(r[0]), "=r"(r[1]), "=r"(r[2]), "=r"(r[3]) : "r"(addr));
}
__device__ __forceinline__ void ldsm_x2(uint32_t* r, uint32_t addr) {
    asm volatile("ldmatrix.sync.aligned.m8n8.x2.shared.b16 {%0,%1}, [%2];"
                 : "=r"(r[0]), "=r"(r[1]) : "r"(addr));
}
__device__ __forceinline__ void mma16816(float* c, const uint32_t* a, const uint32_t* b) {
    asm volatile(
        "mma.sync.aligned.m16n8k16.row.col.f32.f16.f16.f32 "
        "{%0,%1,%2,%3}, {%4,%5,%6,%7}, {%8,%9}, {%0,%1,%2,%3};"
        : "+f"(c[0]), "+f"(c[1]), "+f"(c[2]), "+f"(c[3])
        : "r"(a[0]), "r"(a[1]), "r"(a[2]), "r"(a[3]), "r"(b[0]), "r"(b[1]));
}
__device__ __forceinline__ void lse_merge(float& mx, float& sm, float omx, float osm) {
    float nm = fmaxf(mx, omx);
    float e1 = (mx  > NEG_INF) ? expf(mx  - nm) : 0.f;
    float e2 = (omx > NEG_INF) ? expf(omx - nm) : 0.f;
    sm = sm * e1 + osm * e2;
    mx = nm;
}

#define SROW 40  // smem row stride in halves (conflict-free ldmatrix)

__global__ __launch_bounds__(256) void k_gemm_mma() {
    __shared__ __half sAhi[128 * SROW], sAlo[128 * SROW];
    __shared__ __half sBhi[128 * SROW], sBlo[128 * SROW];
    int M = g_M, N = g_nodeCount + 2;
    int m0 = blockIdx.y * 128, n0 = blockIdx.x * 128;
    if (m0 >= M || n0 >= N) return;

    int tid = threadIdx.x, lane = tid & 31, warp = tid >> 5;
    int wm = warp >> 2, wn = warp & 3;

    float c[4][4][4];
#pragma unroll
    for (int i = 0; i < 4; i++)
#pragma unroll
        for (int j = 0; j < 4; j++)
#pragma unroll
            for (int r = 0; r < 4; r++) c[i][j][r] = 0.f;

    uint32_t aBase = smem_u32(sAhi), alBase = smem_u32(sAlo);
    uint32_t bBase = smem_u32(sBhi), blBase = smem_u32(sBlo);

    int aRow = wm * 64 + (lane & 15);
    int aCol = 8 * (lane >> 4);
    int l16 = lane & 15;
    int bCol = 8 * (l16 >> 3);

    for (int kc = 0; kc < 8; kc++) {
        __syncthreads();
#pragma unroll
        for (int s = 0; s < 2; s++) {
            int id = tid + s * 256;
            int row = id >> 2, kg = id & 3;
            size_t goff = (size_t)row * EE + kc * 32 + kg * 8;
            int soff = row * SROW + kg * 8;
            *(uint4*)&sAhi[soff] = *(const uint4*)&g_Ahi[(size_t)m0 * EE + goff];
            *(uint4*)&sAlo[soff] = *(const uint4*)&g_Alo[(size_t)m0 * EE + goff];
            *(uint4*)&sBhi[soff] = *(const uint4*)&g_Bhi[(size_t)n0 * EE + goff];
            *(uint4*)&sBlo[soff] = *(const uint4*)&g_Blo[(size_t)n0 * EE + goff];
        }
        __syncthreads();

#pragma unroll
        for (int k16 = 0; k16 < 2; k16++) {
            int kb = k16 * 16;
            uint32_t ahi[4][4], bhi[4][2], tmp[4][2], alo[4][4];
#pragma unroll
            for (int mt = 0; mt < 4; mt++)
                ldsm_x4(ahi[mt], aBase + ((aRow + mt * 16) * SROW + kb + aCol) * 2);
#pragma unroll
            for (int nt = 0; nt < 4; nt++)
                ldsm_x2(bhi[nt], bBase + ((wn * 32 + nt * 8 + (l16 & 7)) * SROW + kb + bCol) * 2);
#pragma unroll
            for (int mt = 0; mt < 4; mt++)
#pragma unroll
                for (int nt = 0; nt < 4; nt++) mma16816(c[mt][nt], ahi[mt], bhi[nt]);
#pragma unroll
            for (int nt = 0; nt < 4; nt++)
                ldsm_x2(tmp[nt], blBase + ((wn * 32 + nt * 8 + (l16 & 7)) * SROW + kb + bCol) * 2);
#pragma unroll
            for (int mt = 0; mt < 4; mt++)
#pragma unroll
                for (int nt = 0; nt < 4; nt++) mma16816(c[mt][nt], ahi[mt], tmp[nt]);
#pragma unroll
            for (int mt = 0; mt < 4; mt++)
                ldsm_x4(alo[mt], alBase + ((aRow + mt * 16) * SROW + kb + aCol) * 2);
#pragma unroll
            for (int mt = 0; mt < 4; mt++)
#pragma unroll
                for (int nt = 0; nt < 4; nt++) mma16816(c[mt][nt], alo[mt], bhi[nt]);
        }
    }

    // fused epilogue: per-row (max, sumexp) partials over this 128-col tile
    __syncthreads();
    float* sPm = (float*)sAhi;   // 128*4 floats
    float* sPs = (float*)sAlo;
    int nbase0 = n0 + wn * 32 + 2 * (lane & 3);
#pragma unroll
    for (int mt = 0; mt < 4; mt++) {
#pragma unroll
        for (int h = 0; h < 2; h++) {
            float mx = NEG_INF, sm = 0.f;
#pragma unroll
            for (int nt = 0; nt < 4; nt++)
#pragma unroll
                for (int p = 0; p < 2; p++) {
                    int n = nbase0 + nt * 8 + p;
                    float v = c[mt][nt][h * 2 + p];
                    if (n < N && v > mx) mx = v;
                }
#pragma unroll
            for (int nt = 0; nt < 4; nt++)
#pragma unroll
                for (int p = 0; p < 2; p++) {
                    int n = nbase0 + nt * 8 + p;
                    float v = c[mt][nt][h * 2 + p];
                    if (n < N) sm += expf(v - mx);
                }
#pragma unroll
            for (int o = 1; o <= 2; o <<= 1) {
                float omx = __shfl_xor_sync(0xffffffffu, mx, o);
                float osm = __shfl_xor_sync(0xffffffffu, sm, o);
                lse_merge(mx, sm, omx, osm);
            }
            if ((lane & 3) == 0) {
                int rl = wm * 64 + mt * 16 + (lane >> 2) + 8 * h;
                sPm[rl * 4 + wn] = mx;
                sPs[rl * 4 + wn] = sm;
            }
        }
    }
    __syncthreads();
    if (tid < 128) {
        float mx = NEG_INF, sm = 0.f;
#pragma unroll
        for (int w = 0; w < 4; w++) lse_merge(mx, sm, sPm[tid * 4 + w], sPs[tid * 4 + w]);
        g_pmax[(size_t)(m0 + tid) * 64 + blockIdx.x] = mx;
        g_psum[(size_t)(m0 + tid) * 64 + blockIdx.x] = sm;
    }
}

// merge per-tile partials + exact fp32 target logit; one warp per row
__global__ __launch_bounds__(256) void k_lse2() {
    int w = (blockIdx.x * 256 + threadIdx.x) >> 5;
    int lane = threadIdx.x & 31;
    if (w >= g_M) return;
    int N = g_nodeCount + 2;
    int nTiles = (N + 127) >> 7;
    float mx = NEG_INF, sm = 0.f;
    for (int j = lane; j < nTiles; j += 32)
        lse_merge(mx, sm, g_pmax[(size_t)w * 64 + j], g_psum[(size_t)w * 64 + j]);
#pragma unroll
    for (int o = 16; o; o >>= 1) {
        float omx = __shfl_xor_sync(0xffffffffu, mx, o);
        float osm = __shfl_xor_sync(0xffffffffu, sm, o);
        lse_merge(mx, sm, omx, osm);
    }
    int t0 = g_targets[w * 3];
    float d = warp_dot(&g_outs[(size_t)w * EE], &g_feats[(size_t)t0 * EE]);
    if (lane == 0) g_rowloss[w] = mx + logf(sm) - d;
}

__global__ __launch_bounds__(1024) void k_reduce(float* __restrict__ out) {
    __shared__ float sh[1024];
    int M = g_M;
    float s = 0.f;
    for (int i = threadIdx.x; i < M; i += 1024) s += g_rowloss[i];
    sh[threadIdx.x] = s; __syncthreads();
    for (int o = 512; o; o >>= 1) { if (threadIdx.x < o) sh[threadIdx.x] += sh[threadIdx.x + o]; __syncthreads(); }
    if (threadIdx.x == 0) out[0] = sh[0] / (float)M;
}

// ----------------- launcher -----------------
extern "C" void kernel_launch(void* const* d_in, const int* in_sizes, int n_in,
                              void* d_out, int out_size) {
    const int*   x      = (const int*)  d_in[0];
    const float* emb    = (const float*)d_in[1];
    const float* comp_l = (const float*)d_in[2];
    const float* comp_r = (const float*)d_in[3];
    const float* cb     = (const float*)d_in[4];
    const float* sos    = (const float*)d_in[5];
    const float* eos    = (const float*)d_in[6];
    int NV = in_sizes[1] / EE;  // vocab size (pad token = NV-1)

    k_zero<<<121, 256>>>();
    k_mark<<<16, 256>>>(x);
    k_rank<<<1, 1024>>>(NV);
    k_init_index<<<16, 256>>>(x, NV);
    k_init_nodes<<<4096, 256>>>(emb);
    k_init_cos<<<504, 256>>>();
    k_tree<<<2, 1024>>>(comp_l, comp_r, cb);
    k_finalize<<<2, 256>>>(sos, eos);
    k_outs<<<MAXM, 256>>>(comp_l, comp_r, cb);
    k_cvtB<<<MAXN, 256>>>();
    k_gemm_mma<<<dim3(64, 64), 256>>>();
    k_lse2<<<1024, 256>>>();
    k_reduce<<<1, 1024>>>((float*)d_out);
}

// round 15
// speedup vs baseline: 1.3403x; 1.3403x over previous
#include <cuda_runtime.h>
#include <cuda_fp16.h>
#include <cstdint>
#include <math.h>

#define BB 64
#define LL 64
#define EE 256
#define MAXN 8192
#define MAXM 8192
#define HASHSZ 8192
#define NEG_INF (__int_as_float(0xff800000))

// ----------------- device-global state (no runtime allocation) -----------------
__device__ float g_feats[MAXN * EE];            // node features (fp32)
__device__ float g_norm[MAXN];                  // node norms (tokens + composed)
__device__ float g_outs[MAXM * EE];             // composed context vectors (fp32)
__device__ float g_logits[(size_t)MAXM * MAXN]; // M x N logits (row stride MAXN)
__device__ __half g_Ahi[MAXM * EE];             // fp16 hi/lo split of g_outs
__device__ __half g_Alo[MAXM * EE];
__device__ __half g_Bhi[MAXN * EE];             // fp16 hi/lo split of g_feats
__device__ __half g_Blo[MAXN * EE];
__device__ int   g_rank[30720];
__device__ int   g_tokens[MAXN];
__device__ int   g_index[BB * LL];
__device__ float g_cos[BB * LL];
__device__ int   g_hkey[HASHSZ];
__device__ int   g_hval[HASHSZ];
__device__ int   g_targets[MAXM * 3];
__device__ int   g_M;
__device__ int   g_nodeCount;
__device__ int   g_cnt;
__device__ float g_rowloss[MAXM];

__device__ __forceinline__ float sigmoidf_(float x) { return 1.f / (1.f + expf(-x)); }

__device__ __forceinline__ float warp_dot(const float* a, const float* b) {
    int lane = threadIdx.x & 31;
    float s = 0.f;
#pragma unroll
    for (int k = 0; k < 8; k++) { int e = lane + 32 * k; s += a[e] * b[e]; }
#pragma unroll
    for (int o = 16; o; o >>= 1) s += __shfl_xor_sync(0xffffffffu, s, o);
    return s;
}

// ----------------- setup kernels -----------------
__global__ void k_zero() {
    int i = blockIdx.x * blockDim.x + threadIdx.x;
    if (i < 30720) g_rank[i] = 0;
    if (i < HASHSZ) { g_hkey[i] = -1; g_hval[i] = -1; }
    if (i == 0) { g_M = 0; }
}

__global__ void k_mark(const int* __restrict__ x) {
    int i = blockIdx.x * blockDim.x + threadIdx.x;
    if (i < BB * LL) g_rank[x[i]] = 1;
}

__global__ __launch_bounds__(1024) void k_rank(int NV) {
    __shared__ int scan[1024];
    int tid = threadIdx.x;
    const int CH2 = 30;
    int base = tid * CH2;
    unsigned mask = 0;
    for (int i = 0; i < CH2; i++) {
        int v = base + i;
        if (v < NV && g_rank[v]) mask |= (1u << i);
    }
    int cnt = __popc(mask);
    scan[tid] = cnt;
    __syncthreads();
    for (int o = 1; o < 1024; o <<= 1) {
        int add = (tid >= o) ? scan[tid - o] : 0;
        __syncthreads();
        scan[tid] += add;
        __syncthreads();
    }
    int run = scan[tid] - cnt;
    for (int i = 0; i < CH2; i++) {
        int v = base + i;
        if (v < NV) {
            if (mask & (1u << i)) { g_rank[v] = run; g_tokens[run] = v; run++; }
            else g_rank[v] = -1;
        }
    }
    if (tid == 1023) { g_nodeCount = scan[1023] - 1; g_cnt = scan[1023] - 1; }
}

__global__ void k_init_index(const int* __restrict__ x, int NV) {
    int i = blockIdx.x * blockDim.x + threadIdx.x;
    if (i < BB * LL) {
        int v = x[i];
        g_index[i] = (v == NV - 1) ? -1 : g_rank[v];
    }
}

__global__ void k_init_nodes(const float* __restrict__ emb) {
    int i = blockIdx.x;
    if (i >= g_nodeCount) return;
    int e = threadIdx.x;
    float v = emb[(size_t)g_tokens[i] * EE + e];
    g_feats[i * EE + e] = v;
    float s = v * v;
#pragma unroll
    for (int o = 16; o; o >>= 1) s += __shfl_xor_sync(0xffffffffu, s, o);
    __shared__ float red[8];
    if ((e & 31) == 0) red[e >> 5] = s;
    __syncthreads();
    if (e == 0) {
        float t = 0.f;
#pragma unroll
        for (int w = 0; w < 8; w++) t += red[w];
        g_norm[i] = sqrtf(t);
    }
}

__global__ void k_init_cos() {
    int gw = blockIdx.x * 8 + (threadIdx.x >> 5);
    if (gw >= BB * (LL - 1)) return;
    int r = gw / (LL - 1), j = gw % (LL - 1);
    int iR = g_index[r * LL + j + 1];
    float c;
    if (iR < 0) c = NEG_INF;
    else {
        int iL = g_index[r * LL + j];
        float d = warp_dot(&g_feats[iL * EE], &g_feats[iR * EE]);
        c = d / fmaxf(g_norm[iL] * g_norm[iR], 1e-8f);
    }
    if ((threadIdx.x & 31) == 0) g_cos[r * LL + j] = c;
}

// ----------------- async merge tree: 2 CTAs x 32 warps = one warp per row ---------------
// Per-step: prefetch children+neighbor feats BEFORE the hash probe (latency overlap);
// every warp composes nf locally (bitwise-deterministic), so losers never wait on data.
// Norm reads are volatile (L1-bypass): g_norm packs 32 nodes/line, so a plain load
// could hit a stale L1 line for a node created on the other CTA's SM.
__global__ __launch_bounds__(1024) void k_tree(const float* __restrict__ comp_l,
                                               const float* __restrict__ comp_r,
                                               const float* __restrict__ cb) {
    __shared__ int   s_rIdx[32 * 66];
    __shared__ float s_rCos[32 * 64];
    __shared__ int s_len[64], s_base[64];

    int tid = threadIdx.x, lane = tid & 31, w = tid >> 5;
    int cta = blockIdx.x;
    int r = cta * 32 + w;             // this warp's row
    float slv = sigmoidf_(comp_l[lane & 15]);
    float srv = sigmoidf_(comp_r[lane & 15]);
    float cbv = cb[lane & 15];

    // lens for ALL rows (deterministic target bases, computed per-CTA)
    if (tid < 64) {
        int cnt = 0;
        for (int j = 0; j < 64; j++) cnt += (g_index[tid * 64 + j] != -1);
        s_len[tid] = cnt;
    }
    __syncthreads();
    if (tid == 0) {
        int acc = 0;
        for (int q = 0; q < 64; q++) { s_base[q] = acc; acc += 2 * (s_len[q] - 1); }
        if (cta == 0) g_M = acc;
    }
    // load this CTA's 32 rows
    {
        int i0 = g_index[r * 64 + lane];
        int i1 = g_index[r * 64 + lane + 32];
        s_rIdx[w * 66 + lane] = i0;
        s_rIdx[w * 66 + lane + 32] = i1;
        s_rCos[w * 64 + lane] = g_cos[r * 64 + lane];
        if (lane <= 30) s_rCos[w * 64 + lane + 32] = g_cos[r * 64 + lane + 32];
    }
    __syncthreads();

    int* rIdx = &s_rIdx[w * 66];
    float* rCos = &s_rCos[w * 64];
    int L = s_len[r];
    int tb0 = s_base[r];

    for (int v = L; v >= 2; --v) {
        // argmax over rCos[0..v-2], first-index tiebreak
        float c0 = (lane <= v - 2) ? rCos[lane] : NEG_INF;
        float c1 = (lane + 32 <= v - 2) ? rCos[lane + 32] : NEG_INF;
        float bv; int bi;
        if (c0 >= c1) { bv = c0; bi = lane; } else { bv = c1; bi = lane + 32; }
#pragma unroll
        for (int o = 16; o; o >>= 1) {
            float ov = __shfl_xor_sync(0xffffffffu, bv, o);
            int   oi = __shfl_xor_sync(0xffffffffu, bi, o);
            if (ov > bv || (ov == bv && oi < bi)) { bv = ov; bi = oi; }
        }
        int ms = bi;
        int l = rIdx[ms], rr = rIdx[ms + 1];
        bool hasA = (ms >= 1);
        bool hasB = (ms <= v - 3);
        int a = hasA ? rIdx[ms - 1] : 0;
        int b = hasB ? rIdx[ms + 2] : 0;   // post-shift right neighbor of the new node
        unsigned key = ((unsigned)l << 13) | (unsigned)rr;

        // ---- issue ALL feature loads BEFORE the probe (overlap latencies) ----
        const float* FL = &g_feats[(size_t)l * EE];
        const float* FR = &g_feats[(size_t)rr * EE];
        const float* FA = &g_feats[(size_t)a * EE];
        const float* FB = &g_feats[(size_t)b * EE];
        float fl[8], fr[8], fa[8], fb[8];
#pragma unroll
        for (int k = 0; k < 8; k++) {
            fl[k] = FL[lane + 32 * k];
            fr[k] = FR[lane + 32 * k];
            fa[k] = FA[lane + 32 * k];
            fb[k] = FB[lane + 32 * k];
        }
        float na_ = *(volatile float*)&g_norm[a];
        float nb_ = *(volatile float*)&g_norm[b];

        // ---- dedup via GLOBAL hash: lane 0 probes/claims (loads still in flight) ----
        int nid = -1, claim = 0; unsigned hh = 0;
        if (lane == 0) {
            unsigned h = (key * 2654435761u) & (HASHSZ - 1);
            for (int p = 0; p < HASHSZ; p++) {
                int old = atomicCAS(&g_hkey[h], -1, (int)key);
                if (old == -1) {
                    claim = 1;
                    nid = atomicAdd(&g_cnt, 1);
                    if (nid >= MAXN) nid = MAXN - 1;  // fail-soft
                    hh = h;
                    break;
                }
                if ((unsigned)old == key) {
                    volatile int* vp = &g_hval[h];
                    int x, t = 0;
                    while ((x = *vp) < 0 && ++t < (1 << 20)) {}
                    nid = (x < 0) ? 0 : x;  // fail-soft
                    break;
                }
                h = (h + 1) & (HASHSZ - 1);
            }
            if (nid < 0) nid = 0;  // fail-soft
        }
        nid   = __shfl_sync(0xffffffffu, nid, 0);
        claim = __shfl_sync(0xffffffffu, claim, 0);
        hh    = __shfl_sync(0xffffffffu, hh, 0);

        // ---- EVERY warp composes locally: bitwise-deterministic, no data wait ----
        float nf[8]; float ss = 0.f;
#pragma unroll
        for (int k = 0; k < 8; k++) {
            float x = fl[k] * slv + fr[k] * srv + cbv;
            nf[k] = x;
            ss += x * x;
        }
#pragma unroll
        for (int o = 16; o; o >>= 1) ss += __shfl_xor_sync(0xffffffffu, ss, o);
        float nn = sqrtf(ss);

        if (claim) {
#pragma unroll
            for (int k = 0; k < 8; k++) g_feats[(size_t)nid * EE + lane + 32 * k] = nf[k];
            if (lane == 0) g_norm[nid] = nn;
            __threadfence();                                   // data visible before publish
            if (lane == 0) *(volatile int*)&g_hval[hh] = nid;  // publish
        }

        // record targets at deterministic per-row offset
        if (lane == 0) {
            int ls = hasA ? a : -1;
            int rs = (ms + 2 >= v) ? ((L == 64) ? -2 : -1) : rIdx[ms + 2];
            int tb = tb0 + 2 * (L - v);
            g_targets[tb * 3 + 0] = l;  g_targets[tb * 3 + 1] = ls; g_targets[tb * 3 + 2] = rr;
            g_targets[tb * 3 + 3] = rr; g_targets[tb * 3 + 4] = l;  g_targets[tb * 3 + 5] = rs;
        }

        // shift arrays left past ms (read-before-write within warp)
        int j0 = lane, j1 = lane + 32;
        int ni0 = 0, ni1 = 0; float nc0 = 0.f, nc1 = 0.f;
        if (j0 <= v - 2) ni0 = (j0 == ms) ? nid : rIdx[j0 + (j0 > ms)];
        if (j1 <= v - 2) ni1 = (j1 == ms) ? nid : rIdx[j1 + (j1 > ms)];
        if (j0 <= v - 3) nc0 = (j0 < ms - 1) ? rCos[j0] : ((j0 > ms) ? rCos[j0 + 1] : 0.f);
        if (j1 <= v - 3) nc1 = (j1 < ms - 1) ? rCos[j1] : ((j1 > ms) ? rCos[j1 + 1] : 0.f);
        __syncwarp();
        if (j0 <= v - 2) rIdx[j0] = ni0;
        if (j1 <= v - 2) rIdx[j1] = ni1;
        if (j0 <= v - 3) rCos[j0] = nc0;
        if (j1 <= v - 3) rCos[j1] = nc1;
        __syncwarp();

        // recompute the <=2 affected cosines from prefetched registers (no reloads)
        if (hasA) {
            float s = 0.f;
#pragma unroll
            for (int k = 0; k < 8; k++) s += nf[k] * fa[k];
#pragma unroll
            for (int o = 16; o; o >>= 1) s += __shfl_xor_sync(0xffffffffu, s, o);
            float c = s / fmaxf(na_ * nn, 1e-8f);
            if (lane == 0) rCos[ms - 1] = c;
        }
        if (hasB) {
            float s = 0.f;
#pragma unroll
            for (int k = 0; k < 8; k++) s += nf[k] * fb[k];
#pragma unroll
            for (int o = 16; o; o >>= 1) s += __shfl_xor_sync(0xffffffffu, s, o);
            float c = s / fmaxf(nn * nb_, 1e-8f);
            if (lane == 0) rCos[ms] = c;
        }
        __syncwarp();
    }
}

// append eos (N-2) and sos (N-1); finalize node count from global counter
__global__ void k_finalize(const float* __restrict__ sos, const float* __restrict__ eos) {
    int nc = g_cnt;
    int e = threadIdx.x;
    if (blockIdx.x == 0) {
        g_feats[nc * EE + e] = eos[e];
        if (e == 0) g_nodeCount = nc;
    } else {
        g_feats[(nc + 1) * EE + e] = sos[e];
    }
}

// compose contexts + fp16 hi/lo split in one pass
__global__ void k_outs(const float* __restrict__ comp_l, const float* __restrict__ comp_r,
                       const float* __restrict__ cb) {
    int m = blockIdx.x;
    if (m >= g_M) return;
    int N = g_nodeCount + 2;
    int e = threadIdx.x;
    int t1 = g_targets[m * 3 + 1]; if (t1 < 0) t1 += N;
    int t2 = g_targets[m * 3 + 2]; if (t2 < 0) t2 += N;
    int c = e & 15;
    float sl = sigmoidf_(comp_l[c]), sr = sigmoidf_(comp_r[c]);
    float o = g_feats[t1 * EE + e] * sl + g_feats[t2 * EE + e] * sr + cb[c];
    g_outs[m * EE + e] = o;
    __half h = __float2half_rn(o);
    g_Ahi[m * EE + e] = h;
    g_Alo[m * EE + e] = __float2half_rn(o - __half2float(h));
}

__global__ __launch_bounds__(256) void k_cvtB() {
    int i = blockIdx.x * 256 + threadIdx.x;
    float v = g_feats[i];
    __half h = __float2half_rn(v);
    g_Bhi[i] = h;
    g_Blo[i] = __float2half_rn(v - __half2float(h));
}

// ----------------- mma.sync GEMM (round-11 version, plain logits store) -----------------
__device__ __forceinline__ uint32_t smem_u32(const void* p) {
    uint32_t a;
    asm("{ .reg .u64 t; cvta.to.shared.u64 t, %1; cvt.u32.u64 %0, t; }" : "=r"(a) : "l"(p));
    return a;
}
__device__ __forceinline__ void ldsm_x4(uint32_t* r, uint32_t addr) {
    asm volatile("ldmatrix.sync.aligned.m8n8.x4.shared.b16 {%0,%1,%2,%3}, [%4];"
                 : "=r"(r[0]), "=r"(r[1]), "=r"(r[2]), "=r"(r[3]) : "r"(addr));
}
__device__ __forceinline__ void ldsm_x2(uint32_t* r, uint32_t addr) {
    asm volatile("ldmatrix.sync.aligned.m8n8.x2.shared.b16 {%0,%1}, [%2];"
                 : "=r"(r[0]), "=r"(r[1]) : "r"(addr));
}
__device__ __forceinline__ void mma16816(float* c, const uint32_t* a, const uint32_t* b) {
    asm volatile(
        "mma.sync.aligned.m16n8k16.row.col.f32.f16.f16.f32 "
        "{%0,%1,%2,%3}, {%4,%5,%6,%7}, {%8,%9}, {%0,%1,%2,%3};"
        : "+f"(c[0]), "+f"(c[1]), "+f"(c[2]), "+f"(c[3])
        : "r"(a[0]), "r"(a[1]), "r"(a[2]), "r"(a[3]), "r"(b[0]), "r"(b[1]));
}

#define SROW 40  // smem row stride in halves (conflict-free ldmatrix)

__global__ __launch_bounds__(256) void k_gemm_mma() {
    __shared__ __half sAhi[128 * SROW], sAlo[128 * SROW];
    __shared__ __half sBhi[128 * SROW], sBlo[128 * SROW];
    int M = g_M, N = g_nodeCount + 2;
    int m0 = blockIdx.y * 128, n0 = blockIdx.x * 128;
    if (m0 >= M || n0 >= N) return;

    int tid = threadIdx.x, lane = tid & 31, warp = tid >> 5;
    int wm = warp >> 2, wn = warp & 3;

    float c[4][4][4];
#pragma unroll
    for (int i = 0; i < 4; i++)
#pragma unroll
        for (int j = 0; j < 4; j++)
#pragma unroll
            for (int r = 0; r < 4; r++) c[i][j][r] = 0.f;

    uint32_t aBase = smem_u32(sAhi), alBase = smem_u32(sAlo);
    uint32_t bBase = smem_u32(sBhi), blBase = smem_u32(sBlo);

    int aRow = wm * 64 + (lane & 15);
    int aCol = 8 * (lane >> 4);
    int l16 = lane & 15;
    int bCol = 8 * (l16 >> 3);

    for (int kc = 0; kc < 8; kc++) {
        __syncthreads();
#pragma unroll
        for (int s = 0; s < 2; s++) {
            int id = tid + s * 256;
            int row = id >> 2, kg = id & 3;
            size_t goff = (size_t)row * EE + kc * 32 + kg * 8;
            int soff = row * SROW + kg * 8;
            *(uint4*)&sAhi[soff] = *(const uint4*)&g_Ahi[(size_t)m0 * EE + goff];
            *(uint4*)&sAlo[soff] = *(const uint4*)&g_Alo[(size_t)m0 * EE + goff];
            *(uint4*)&sBhi[soff] = *(const uint4*)&g_Bhi[(size_t)n0 * EE + goff];
            *(uint4*)&sBlo[soff] = *(const uint4*)&g_Blo[(size_t)n0 * EE + goff];
        }
        __syncthreads();

#pragma unroll
        for (int k16 = 0; k16 < 2; k16++) {
            int kb = k16 * 16;
            uint32_t ahi[4][4], bhi[4][2], tmp[4][2], alo[4][4];
#pragma unroll
            for (int mt = 0; mt < 4; mt++)
                ldsm_x4(ahi[mt], aBase + ((aRow + mt * 16) * SROW + kb + aCol) * 2);
#pragma unroll
            for (int nt = 0; nt < 4; nt++)
                ldsm_x2(bhi[nt], bBase + ((wn * 32 + nt * 8 + (l16 & 7)) * SROW + kb + bCol) * 2);
#pragma unroll
            for (int mt = 0; mt < 4; mt++)
#pragma unroll
                for (int nt = 0; nt < 4; nt++) mma16816(c[mt][nt], ahi[mt], bhi[nt]);
#pragma unroll
            for (int nt = 0; nt < 4; nt++)
                ldsm_x2(tmp[nt], blBase + ((wn * 32 + nt * 8 + (l16 & 7)) * SROW + kb + bCol) * 2);
#pragma unroll
            for (int mt = 0; mt < 4; mt++)
#pragma unroll
                for (int nt = 0; nt < 4; nt++) mma16816(c[mt][nt], ahi[mt], tmp[nt]);
#pragma unroll
            for (int mt = 0; mt < 4; mt++)
                ldsm_x4(alo[mt], alBase + ((aRow + mt * 16) * SROW + kb + aCol) * 2);
#pragma unroll
            for (int mt = 0; mt < 4; mt++)
#pragma unroll
                for (int nt = 0; nt < 4; nt++) mma16816(c[mt][nt], alo[mt], bhi[nt]);
        }
    }

#pragma unroll
    for (int mt = 0; mt < 4; mt++) {
#pragma unroll
        for (int nt = 0; nt < 4; nt++) {
            int m = m0 + wm * 64 + mt * 16 + (lane >> 2);
            int n = n0 + wn * 32 + nt * 8 + 2 * (lane & 3);
            *(float2*)&g_logits[(size_t)m * MAXN + n] = make_float2(c[mt][nt][0], c[mt][nt][1]);
            *(float2*)&g_logits[(size_t)(m + 8) * MAXN + n] = make_float2(c[mt][nt][2], c[mt][nt][3]);
        }
    }
}

__global__ __launch_bounds__(256) void k_lse() {
    int m = blockIdx.x;
    if (m >= g_M) return;
    int N = g_nodeCount + 2;
    const float* row = &g_logits[(size_t)m * MAXN];
    int tid = threadIdx.x;
    __shared__ float sh[256];
    float mx = NEG_INF;
    for (int j = tid; j < N; j += 256) mx = fmaxf(mx, row[j]);
    sh[tid] = mx; __syncthreads();
    for (int o = 128; o; o >>= 1) { if (tid < o) sh[tid] = fmaxf(sh[tid], sh[tid + o]); __syncthreads(); }
    mx = sh[0]; __syncthreads();
    float se = 0.f;
    for (int j = tid; j < N; j += 256) se += expf(row[j] - mx);
    sh[tid] = se; __syncthreads();
    for (int o = 128; o; o >>= 1) { if (tid < o) sh[tid] += sh[tid + o]; __syncthreads(); }
    if (tid == 0) {
        int t0 = g_targets[m * 3];
        g_rowloss[m] = mx + logf(sh[0]) - row[t0];
    }
}

__global__ __launch_bounds__(1024) void k_reduce(float* __restrict__ out) {
    __shared__ float sh[1024];
    int M = g_M;
    float s = 0.f;
    for (int i = threadIdx.x; i < M; i += 1024) s += g_rowloss[i];
    sh[threadIdx.x] = s; __syncthreads();
    for (int o = 512; o; o >>= 1) { if (threadIdx.x < o) sh[threadIdx.x] += sh[threadIdx.x + o]; __syncthreads(); }
    if (threadIdx.x == 0) out[0] = sh[0] / (float)M;
}

// ----------------- launcher -----------------
extern "C" void kernel_launch(void* const* d_in, const int* in_sizes, int n_in,
                              void* d_out, int out_size) {
    const int*   x      = (const int*)  d_in[0];
    const float* emb    = (const float*)d_in[1];
    const float* comp_l = (const float*)d_in[2];
    const float* comp_r = (const float*)d_in[3];
    const float* cb     = (const float*)d_in[4];
    const float* sos    = (const float*)d_in[5];
    const float* eos    = (const float*)d_in[6];
    int NV = in_sizes[1] / EE;  // vocab size (pad token = NV-1)

    k_zero<<<121, 256>>>();
    k_mark<<<16, 256>>>(x);
    k_rank<<<1, 1024>>>(NV);
    k_init_index<<<16, 256>>>(x, NV);
    k_init_nodes<<<4096, 256>>>(emb);
    k_init_cos<<<504, 256>>>();
    k_tree<<<2, 1024>>>(comp_l, comp_r, cb);
    k_finalize<<<2, 256>>>(sos, eos);
    k_outs<<<MAXM, 256>>>(comp_l, comp_r, cb);
    k_cvtB<<<MAXN, 256>>>();
    k_gemm_mma<<<dim3(64, 64), 256>>>();
    k_lse<<<MAXM, 256>>>();
    k_reduce<<<1, 1024>>>((float*)d_out);
}

// round 16
// speedup vs baseline: 1.3716x; 1.0233x over previous
#include <cuda_runtime.h>
#include <cuda_fp16.h>
#include <cstdint>
#include <math.h>

#define BB 64
#define LL 64
#define EE 256
#define MAXN 8192
#define MAXM 8192
#define HASHSZ 8192
#define NEG_INF (__int_as_float(0xff800000))

// ----------------- device-global state (no runtime allocation) -----------------
__device__ float g_feats[MAXN * EE];            // node features (fp32)
__device__ float g_norm[MAXN];                  // node norms (tokens + composed)
__device__ float g_outs[MAXM * EE];             // composed context vectors (fp32)
__device__ float g_logits[(size_t)MAXM * MAXN]; // M x N logits (row stride MAXN)
__device__ __half g_Ahi[MAXM * EE];             // fp16 hi/lo split of g_outs
__device__ __half g_Alo[MAXM * EE];
__device__ __half g_Bhi[MAXN * EE];             // fp16 hi/lo split of g_feats
__device__ __half g_Blo[MAXN * EE];
__device__ int   g_rank[30720];
__device__ int   g_tokens[MAXN];
__device__ int   g_index[BB * LL];
__device__ float g_cos[BB * LL];
__device__ int   g_hkey[HASHSZ];
__device__ int   g_hval[HASHSZ];
__device__ int   g_targets[MAXM * 3];
__device__ int   g_M;
__device__ int   g_nodeCount;
__device__ int   g_cnt;
__device__ float g_rowloss[MAXM];

__device__ __forceinline__ float sigmoidf_(float x) { return 1.f / (1.f + expf(-x)); }

__device__ __forceinline__ float warp_dot(const float* a, const float* b) {
    int lane = threadIdx.x & 31;
    float s = 0.f;
#pragma unroll
    for (int k = 0; k < 8; k++) { int e = lane + 32 * k; s += a[e] * b[e]; }
#pragma unroll
    for (int o = 16; o; o >>= 1) s += __shfl_xor_sync(0xffffffffu, s, o);
    return s;
}

// ----------------- setup kernels -----------------
__global__ void k_zero() {
    int i = blockIdx.x * blockDim.x + threadIdx.x;
    if (i < 30720) g_rank[i] = 0;
    if (i < HASHSZ) { g_hkey[i] = -1; g_hval[i] = -1; }
    if (i == 0) { g_M = 0; }
}

__global__ void k_mark(const int* __restrict__ x) {
    int i = blockIdx.x * blockDim.x + threadIdx.x;
    if (i < BB * LL) g_rank[x[i]] = 1;
}

__global__ __launch_bounds__(1024) void k_rank(int NV) {
    __shared__ int scan[1024];
    int tid = threadIdx.x;
    const int CH2 = 30;
    int base = tid * CH2;
    unsigned mask = 0;
    for (int i = 0; i < CH2; i++) {
        int v = base + i;
        if (v < NV && g_rank[v]) mask |= (1u << i);
    }
    int cnt = __popc(mask);
    scan[tid] = cnt;
    __syncthreads();
    for (int o = 1; o < 1024; o <<= 1) {
        int add = (tid >= o) ? scan[tid - o] : 0;
        __syncthreads();
        scan[tid] += add;
        __syncthreads();
    }
    int run = scan[tid] - cnt;
    for (int i = 0; i < CH2; i++) {
        int v = base + i;
        if (v < NV) {
            if (mask & (1u << i)) { g_rank[v] = run; g_tokens[run] = v; run++; }
            else g_rank[v] = -1;
        }
    }
    if (tid == 1023) { g_nodeCount = scan[1023] - 1; g_cnt = scan[1023] - 1; }
}

__global__ void k_init_index(const int* __restrict__ x, int NV) {
    int i = blockIdx.x * blockDim.x + threadIdx.x;
    if (i < BB * LL) {
        int v = x[i];
        g_index[i] = (v == NV - 1) ? -1 : g_rank[v];
    }
}

__global__ void k_init_nodes(const float* __restrict__ emb) {
    int i = blockIdx.x;
    if (i >= g_nodeCount) return;
    int e = threadIdx.x;
    float v = emb[(size_t)g_tokens[i] * EE + e];
    g_feats[i * EE + e] = v;
    float s = v * v;
#pragma unroll
    for (int o = 16; o; o >>= 1) s += __shfl_xor_sync(0xffffffffu, s, o);
    __shared__ float red[8];
    if ((e & 31) == 0) red[e >> 5] = s;
    __syncthreads();
    if (e == 0) {
        float t = 0.f;
#pragma unroll
        for (int w = 0; w < 8; w++) t += red[w];
        g_norm[i] = sqrtf(t);
    }
}

__global__ void k_init_cos() {
    int gw = blockIdx.x * 8 + (threadIdx.x >> 5);
    if (gw >= BB * (LL - 1)) return;
    int r = gw / (LL - 1), j = gw % (LL - 1);
    int iR = g_index[r * LL + j + 1];
    float c;
    if (iR < 0) c = NEG_INF;
    else {
        int iL = g_index[r * LL + j];
        float d = warp_dot(&g_feats[iL * EE], &g_feats[iR * EE]);
        c = d / fmaxf(g_norm[iL] * g_norm[iR], 1e-8f);
    }
    if ((threadIdx.x & 31) == 0) g_cos[r * LL + j] = c;
}

// ----------------- async merge tree: 2 CTAs x 32 warps = one warp per row ---------------
// Per-step: prefetch children+neighbor feats BEFORE the hash probe (latency overlap);
// every warp composes nf locally (bitwise-deterministic), so losers never wait on data.
// Norm reads are volatile (L1-bypass): g_norm packs 32 nodes/line, so a plain load
// could hit a stale L1 line for a node created on the other CTA's SM.
__global__ __launch_bounds__(1024) void k_tree(const float* __restrict__ comp_l,
                                               const float* __restrict__ comp_r,
                                               const float* __restrict__ cb) {
    __shared__ int   s_rIdx[32 * 66];
    __shared__ float s_rCos[32 * 64];
    __shared__ int s_len[64], s_base[64];

    int tid = threadIdx.x, lane = tid & 31, w = tid >> 5;
    int cta = blockIdx.x;
    int r = cta * 32 + w;             // this warp's row
    float slv = sigmoidf_(comp_l[lane & 15]);
    float srv = sigmoidf_(comp_r[lane & 15]);
    float cbv = cb[lane & 15];

    // lens for ALL rows (deterministic target bases, computed per-CTA)
    if (tid < 64) {
        int cnt = 0;
        for (int j = 0; j < 64; j++) cnt += (g_index[tid * 64 + j] != -1);
        s_len[tid] = cnt;
    }
    __syncthreads();
    if (tid == 0) {
        int acc = 0;
        for (int q = 0; q < 64; q++) { s_base[q] = acc; acc += 2 * (s_len[q] - 1); }
        if (cta == 0) g_M = acc;
    }
    // load this CTA's 32 rows
    {
        int i0 = g_index[r * 64 + lane];
        int i1 = g_index[r * 64 + lane + 32];
        s_rIdx[w * 66 + lane] = i0;
        s_rIdx[w * 66 + lane + 32] = i1;
        s_rCos[w * 64 + lane] = g_cos[r * 64 + lane];
        if (lane <= 30) s_rCos[w * 64 + lane + 32] = g_cos[r * 64 + lane + 32];
    }
    __syncthreads();

    int* rIdx = &s_rIdx[w * 66];
    float* rCos = &s_rCos[w * 64];
    int L = s_len[r];
    int tb0 = s_base[r];

    for (int v = L; v >= 2; --v) {
        // argmax over rCos[0..v-2], first-index tiebreak
        float c0 = (lane <= v - 2) ? rCos[lane] : NEG_INF;
        float c1 = (lane + 32 <= v - 2) ? rCos[lane + 32] : NEG_INF;
        float bv; int bi;
        if (c0 >= c1) { bv = c0; bi = lane; } else { bv = c1; bi = lane + 32; }
#pragma unroll
        for (int o = 16; o; o >>= 1) {
            float ov = __shfl_xor_sync(0xffffffffu, bv, o);
            int   oi = __shfl_xor_sync(0xffffffffu, bi, o);
            if (ov > bv || (ov == bv && oi < bi)) { bv = ov; bi = oi; }
        }
        int ms = bi;
        int l = rIdx[ms], rr = rIdx[ms + 1];
        bool hasA = (ms >= 1);
        bool hasB = (ms <= v - 3);
        int a = hasA ? rIdx[ms - 1] : 0;
        int b = hasB ? rIdx[ms + 2] : 0;   // post-shift right neighbor of the new node
        unsigned key = ((unsigned)l << 13) | (unsigned)rr;

        // ---- issue ALL feature loads BEFORE the probe (overlap latencies) ----
        const float* FL = &g_feats[(size_t)l * EE];
        const float* FR = &g_feats[(size_t)rr * EE];
        const float* FA = &g_feats[(size_t)a * EE];
        const float* FB = &g_feats[(size_t)b * EE];
        float fl[8], fr[8], fa[8], fb[8];
#pragma unroll
        for (int k = 0; k < 8; k++) {
            fl[k] = FL[lane + 32 * k];
            fr[k] = FR[lane + 32 * k];
            fa[k] = FA[lane + 32 * k];
            fb[k] = FB[lane + 32 * k];
        }
        float na_ = *(volatile float*)&g_norm[a];
        float nb_ = *(volatile float*)&g_norm[b];

        // ---- dedup via GLOBAL hash: lane 0 probes/claims (loads still in flight) ----
        int nid = -1, claim = 0; unsigned hh = 0;
        if (lane == 0) {
            unsigned h = (key * 2654435761u) & (HASHSZ - 1);
            for (int p = 0; p < HASHSZ; p++) {
                int old = atomicCAS(&g_hkey[h], -1, (int)key);
                if (old == -1) {
                    claim = 1;
                    nid = atomicAdd(&g_cnt, 1);
                    if (nid >= MAXN) nid = MAXN - 1;  // fail-soft
                    hh = h;
                    break;
                }
                if ((unsigned)old == key) {
                    volatile int* vp = &g_hval[h];
                    int x, t = 0;
                    while ((x = *vp) < 0 && ++t < (1 << 20)) {}
                    nid = (x < 0) ? 0 : x;  // fail-soft
                    break;
                }
                h = (h + 1) & (HASHSZ - 1);
            }
            if (nid < 0) nid = 0;  // fail-soft
        }
        nid   = __shfl_sync(0xffffffffu, nid, 0);
        claim = __shfl_sync(0xffffffffu, claim, 0);
        hh    = __shfl_sync(0xffffffffu, hh, 0);

        // ---- EVERY warp composes locally: bitwise-deterministic, no data wait ----
        float nf[8]; float ss = 0.f;
#pragma unroll
        for (int k = 0; k < 8; k++) {
            float x = fl[k] * slv + fr[k] * srv + cbv;
            nf[k] = x;
            ss += x * x;
        }
#pragma unroll
        for (int o = 16; o; o >>= 1) ss += __shfl_xor_sync(0xffffffffu, ss, o);
        float nn = sqrtf(ss);

        if (claim) {
#pragma unroll
            for (int k = 0; k < 8; k++) g_feats[(size_t)nid * EE + lane + 32 * k] = nf[k];
            if (lane == 0) g_norm[nid] = nn;
            __threadfence();                                   // data visible before publish
            if (lane == 0) *(volatile int*)&g_hval[hh] = nid;  // publish
        }

        // record targets at deterministic per-row offset
        if (lane == 0) {
            int ls = hasA ? a : -1;
            int rs = (ms + 2 >= v) ? ((L == 64) ? -2 : -1) : rIdx[ms + 2];
            int tb = tb0 + 2 * (L - v);
            g_targets[tb * 3 + 0] = l;  g_targets[tb * 3 + 1] = ls; g_targets[tb * 3 + 2] = rr;
            g_targets[tb * 3 + 3] = rr; g_targets[tb * 3 + 4] = l;  g_targets[tb * 3 + 5] = rs;
        }

        // shift arrays left past ms (read-before-write within warp)
        int j0 = lane, j1 = lane + 32;
        int ni0 = 0, ni1 = 0; float nc0 = 0.f, nc1 = 0.f;
        if (j0 <= v - 2) ni0 = (j0 == ms) ? nid : rIdx[j0 + (j0 > ms)];
        if (j1 <= v - 2) ni1 = (j1 == ms) ? nid : rIdx[j1 + (j1 > ms)];
        if (j0 <= v - 3) nc0 = (j0 < ms - 1) ? rCos[j0] : ((j0 > ms) ? rCos[j0 + 1] : 0.f);
        if (j1 <= v - 3) nc1 = (j1 < ms - 1) ? rCos[j1] : ((j1 > ms) ? rCos[j1 + 1] : 0.f);
        __syncwarp();
        if (j0 <= v - 2) rIdx[j0] = ni0;
        if (j1 <= v - 2) rIdx[j1] = ni1;
        if (j0 <= v - 3) rCos[j0] = nc0;
        if (j1 <= v - 3) rCos[j1] = nc1;
        __syncwarp();

        // recompute the <=2 affected cosines from prefetched registers (no reloads)
        if (hasA) {
            float s = 0.f;
#pragma unroll
            for (int k = 0; k < 8; k++) s += nf[k] * fa[k];
#pragma unroll
            for (int o = 16; o; o >>= 1) s += __shfl_xor_sync(0xffffffffu, s, o);
            float c = s / fmaxf(na_ * nn, 1e-8f);
            if (lane == 0) rCos[ms - 1] = c;
        }
        if (hasB) {
            float s = 0.f;
#pragma unroll
            for (int k = 0; k < 8; k++) s += nf[k] * fb[k];
#pragma unroll
            for (int o = 16; o; o >>= 1) s += __shfl_xor_sync(0xffffffffu, s, o);
            float c = s / fmaxf(nn * nb_, 1e-8f);
            if (lane == 0) rCos[ms] = c;
        }
        __syncwarp();
    }
}

// append eos (N-2) and sos (N-1); finalize node count from global counter
__global__ void k_finalize(const float* __restrict__ sos, const float* __restrict__ eos) {
    int nc = g_cnt;
    int e = threadIdx.x;
    if (blockIdx.x == 0) {
        g_feats[nc * EE + e] = eos[e];
        if (e == 0) g_nodeCount = nc;
    } else {
        g_feats[(nc + 1) * EE + e] = sos[e];
    }
}

// compose contexts + fp16 hi/lo split in one pass
__global__ void k_outs(const float* __restrict__ comp_l, const float* __restrict__ comp_r,
                       const float* __restrict__ cb) {
    int m = blockIdx.x;
    if (m >= g_M) return;
    int N = g_nodeCount + 2;
    int e = threadIdx.x;
    int t1 = g_targets[m * 3 + 1]; if (t1 < 0) t1 += N;
    int t2 = g_targets[m * 3 + 2]; if (t2 < 0) t2 += N;
    int c = e & 15;
    float sl = sigmoidf_(comp_l[c]), sr = sigmoidf_(comp_r[c]);
    float o = g_feats[t1 * EE + e] * sl + g_feats[t2 * EE + e] * sr + cb[c];
    g_outs[m * EE + e] = o;
    __half h = __float2half_rn(o);
    g_Ahi[m * EE + e] = h;
    g_Alo[m * EE + e] = __float2half_rn(o - __half2float(h));
}

__global__ __launch_bounds__(256) void k_cvtB() {
    int i = blockIdx.x * 256 + threadIdx.x;
    float v = g_feats[i];
    __half h = __float2half_rn(v);
    g_Bhi[i] = h;
    g_Blo[i] = __float2half_rn(v - __half2float(h));
}

// ----------------- mma.sync GEMM: A-fragment register reuse, 2 CTAs/SM -----------------
__device__ __forceinline__ uint32_t smem_u32(const void* p) {
    uint32_t a;
    asm("{ .reg .u64 t; cvta.to.shared.u64 t, %1; cvt.u32.u64 %0, t; }" : "=r"(a) : "l"(p));
    return a;
}
__device__ __forceinline__ void ldsm_x4(uint32_t* r, uint32_t addr) {
    asm volatile("ldmatrix.sync.aligned.m8n8.x4.shared.b16 {%0,%1,%2,%3}, [%4];"
                 : "=r"(r[0]), "=r"(r[1]), "=r"(r[2]), "=r"(r[3]) : "r"(addr));
}
__device__ __forceinline__ void ldsm_x2(uint32_t* r, uint32_t addr) {
    asm volatile("ldmatrix.sync.aligned.m8n8.x2.shared.b16 {%0,%1}, [%2];"
                 : "=r"(r[0]), "=r"(r[1]) : "r"(addr));
}
__device__ __forceinline__ void mma16816(float* c, const uint32_t* a, const uint32_t* b) {
    asm volatile(
        "mma.sync.aligned.m16n8k16.row.col.f32.f16.f16.f32 "
        "{%0,%1,%2,%3}, {%4,%5,%6,%7}, {%8,%9}, {%0,%1,%2,%3};"
        : "+f"(c[0]), "+f"(c[1]), "+f"(c[2]), "+f"(c[3])
        : "r"(a[0]), "r"(a[1]), "r"(a[2]), "r"(a[3]), "r"(b[0]), "r"(b[1]));
}

#define SROW 40  // smem row stride in halves (conflict-free ldmatrix)

__global__ __launch_bounds__(256, 2) void k_gemm_mma() {
    __shared__ __half sAhi[128 * SROW], sAlo[128 * SROW];
    __shared__ __half sBhi[128 * SROW], sBlo[128 * SROW];
    int M = g_M, N = g_nodeCount + 2;
    int m0 = blockIdx.y * 128, n0 = blockIdx.x * 128;
    if (m0 >= M || n0 >= N) return;

    int tid = threadIdx.x, lane = tid & 31, warp = tid >> 5;
    int wm = warp >> 2, wn = warp & 3;

    float c[4][4][4];
#pragma unroll
    for (int i = 0; i < 4; i++)
#pragma unroll
        for (int j = 0; j < 4; j++)
#pragma unroll
            for (int r = 0; r < 4; r++) c[i][j][r] = 0.f;

    uint32_t aBase = smem_u32(sAhi), alBase = smem_u32(sAlo);
    uint32_t bBase = smem_u32(sBhi), blBase = smem_u32(sBlo);

    int aRow = wm * 64 + (lane & 15);
    int aCol = 8 * (lane >> 4);
    int l16 = lane & 15;
    int bCol = 8 * (l16 >> 3);

    for (int kc = 0; kc < 8; kc++) {
        __syncthreads();
#pragma unroll
        for (int s = 0; s < 2; s++) {
            int id = tid + s * 256;
            int row = id >> 2, kg = id & 3;
            size_t goff = (size_t)row * EE + kc * 32 + kg * 8;
            int soff = row * SROW + kg * 8;
            *(uint4*)&sAhi[soff] = *(const uint4*)&g_Ahi[(size_t)m0 * EE + goff];
            *(uint4*)&sAlo[soff] = *(const uint4*)&g_Alo[(size_t)m0 * EE + goff];
            *(uint4*)&sBhi[soff] = *(const uint4*)&g_Bhi[(size_t)n0 * EE + goff];
            *(uint4*)&sBlo[soff] = *(const uint4*)&g_Blo[(size_t)n0 * EE + goff];
        }
        __syncthreads();

#pragma unroll
        for (int k16 = 0; k16 < 2; k16++) {
            int kb = k16 * 16;
            uint32_t a[4][4], bhi[4][2], tmp[4][2];
            // pass 1: a = Ahi, acc += Ahi*Bhi
#pragma unroll
            for (int mt = 0; mt < 4; mt++)
                ldsm_x4(a[mt], aBase + ((aRow + mt * 16) * SROW + kb + aCol) * 2);
#pragma unroll
            for (int nt = 0; nt < 4; nt++)
                ldsm_x2(bhi[nt], bBase + ((wn * 32 + nt * 8 + (l16 & 7)) * SROW + kb + bCol) * 2);
#pragma unroll
            for (int mt = 0; mt < 4; mt++)
#pragma unroll
                for (int nt = 0; nt < 4; nt++) mma16816(c[mt][nt], a[mt], bhi[nt]);
            // pass 2: acc += Ahi*Blo
#pragma unroll
            for (int nt = 0; nt < 4; nt++)
                ldsm_x2(tmp[nt], blBase + ((wn * 32 + nt * 8 + (l16 & 7)) * SROW + kb + bCol) * 2);
#pragma unroll
            for (int mt = 0; mt < 4; mt++)
#pragma unroll
                for (int nt = 0; nt < 4; nt++) mma16816(c[mt][nt], a[mt], tmp[nt]);
            // pass 3: a = Alo (register reuse), acc += Alo*Bhi
#pragma unroll
            for (int mt = 0; mt < 4; mt++)
                ldsm_x4(a[mt], alBase + ((aRow + mt * 16) * SROW + kb + aCol) * 2);
#pragma unroll
            for (int mt = 0; mt < 4; mt++)
#pragma unroll
                for (int nt = 0; nt < 4; nt++) mma16816(c[mt][nt], a[mt], bhi[nt]);
        }
    }

#pragma unroll
    for (int mt = 0; mt < 4; mt++) {
#pragma unroll
        for (int nt = 0; nt < 4; nt++) {
            int m = m0 + wm * 64 + mt * 16 + (lane >> 2);
            int n = n0 + wn * 32 + nt * 8 + 2 * (lane & 3);
            *(float2*)&g_logits[(size_t)m * MAXN + n] = make_float2(c[mt][nt][0], c[mt][nt][1]);
            *(float2*)&g_logits[(size_t)(m + 8) * MAXN + n] = make_float2(c[mt][nt][2], c[mt][nt][3]);
        }
    }
}

__global__ __launch_bounds__(256) void k_lse() {
    int m = blockIdx.x;
    if (m >= g_M) return;
    int N = g_nodeCount + 2;
    const float* row = &g_logits[(size_t)m * MAXN];
    int tid = threadIdx.x;
    __shared__ float sh[256];
    float mx = NEG_INF;
    for (int j = tid; j < N; j += 256) mx = fmaxf(mx, row[j]);
    sh[tid] = mx; __syncthreads();
    for (int o = 128; o; o >>= 1) { if (tid < o) sh[tid] = fmaxf(sh[tid], sh[tid + o]); __syncthreads(); }
    mx = sh[0]; __syncthreads();
    float se = 0.f;
    for (int j = tid; j < N; j += 256) se += expf(row[j] - mx);
    sh[tid] = se; __syncthreads();
    for (int o = 128; o; o >>= 1) { if (tid < o) sh[tid] += sh[tid + o]; __syncthreads(); }
    if (tid == 0) {
        int t0 = g_targets[m * 3];
        g_rowloss[m] = mx + logf(sh[0]) - row[t0];
    }
}

__global__ __launch_bounds__(1024) void k_reduce(float* __restrict__ out) {
    __shared__ float sh[1024];
    int M = g_M;
    float s = 0.f;
    for (int i = threadIdx.x; i < M; i += 1024) s += g_rowloss[i];
    sh[threadIdx.x] = s; __syncthreads();
    for (int o = 512; o; o >>= 1) { if (threadIdx.x < o) sh[threadIdx.x] += sh[threadIdx.x + o]; __syncthreads(); }
    if (threadIdx.x == 0) out[0] = sh[0] / (float)M;
}

// ----------------- launcher -----------------
extern "C" void kernel_launch(void* const* d_in, const int* in_sizes, int n_in,
                              void* d_out, int out_size) {
    const int*   x      = (const int*)  d_in[0];
    const float* emb    = (const float*)d_in[1];
    const float* comp_l = (const float*)d_in[2];
    const float* comp_r = (const float*)d_in[3];
    const float* cb     = (const float*)d_in[4];
    const float* sos    = (const float*)d_in[5];
    const float* eos    = (const float*)d_in[6];
    int NV = in_sizes[1] / EE;  // vocab size (pad token = NV-1)

    k_zero<<<121, 256>>>();
    k_mark<<<16, 256>>>(x);
    k_rank<<<1, 1024>>>(NV);
    k_init_index<<<16, 256>>>(x, NV);
    k_init_nodes<<<4096, 256>>>(emb);
    k_init_cos<<<504, 256>>>();
    k_tree<<<2, 1024>>>(comp_l, comp_r, cb);
    k_finalize<<<2, 256>>>(sos, eos);
    k_outs<<<MAXM, 256>>>(comp_l, comp_r, cb);
    k_cvtB<<<MAXN, 256>>>();
    k_gemm_mma<<<dim3(64, 64), 256>>>();
    k_lse<<<MAXM, 256>>>();
    k_reduce<<<1, 1024>>>((float*)d_out);
}

// round 17
// speedup vs baseline: 1.3883x; 1.0122x over previous
#include <cuda_runtime.h>
#include <cuda_fp16.h>
#include <cstdint>
#include <math.h>

#define BB 64
#define LL 64
#define EE 256
#define MAXN 8192
#define MAXM 8192
#define HASHSZ 8192
#define NEG_INF (__int_as_float(0xff800000))

// ----------------- device-global state (no runtime allocation) -----------------
__device__ float g_feats[MAXN * EE];            // node features (fp32)
__device__ float g_norm[MAXN];                  // node norms (tokens + composed)
__device__ float g_outs[MAXM * EE];             // composed context vectors (fp32)
__device__ float g_logits[(size_t)MAXM * MAXN]; // M x N logits (row stride MAXN)
__device__ __half g_Ahi[MAXM * EE];             // fp16 hi/lo split of g_outs
__device__ __half g_Alo[MAXM * EE];
__device__ __half g_Bhi[MAXN * EE];             // fp16 hi/lo split of g_feats
__device__ __half g_Blo[MAXN * EE];
__device__ int   g_rank[30720];
__device__ int   g_tokens[MAXN];
__device__ int   g_index[BB * LL];
__device__ float g_cos[BB * LL];
__device__ int   g_hkey[HASHSZ];
__device__ int   g_hval[HASHSZ];
__device__ int   g_targets[MAXM * 3];
__device__ int   g_M;
__device__ int   g_nodeCount;
__device__ int   g_cnt;
__device__ float g_rowloss[MAXM];

__device__ __forceinline__ float sigmoidf_(float x) { return 1.f / (1.f + expf(-x)); }

__device__ __forceinline__ float warp_dot(const float* a, const float* b) {
    int lane = threadIdx.x & 31;
    float s = 0.f;
#pragma unroll
    for (int k = 0; k < 8; k++) { int e = lane + 32 * k; s += a[e] * b[e]; }
#pragma unroll
    for (int o = 16; o; o >>= 1) s += __shfl_xor_sync(0xffffffffu, s, o);
    return s;
}

// ----------------- setup kernels -----------------
__global__ void k_zero() {
    int i = blockIdx.x * blockDim.x + threadIdx.x;
    if (i < 30720) g_rank[i] = 0;
    if (i < HASHSZ) { g_hkey[i] = -1; g_hval[i] = -1; }
    if (i == 0) { g_M = 0; }
}

__global__ void k_mark(const int* __restrict__ x) {
    int i = blockIdx.x * blockDim.x + threadIdx.x;
    if (i < BB * LL) g_rank[x[i]] = 1;
}

__global__ __launch_bounds__(1024) void k_rank(int NV) {
    __shared__ int scan[1024];
    int tid = threadIdx.x;
    const int CH2 = 30;
    int base = tid * CH2;
    unsigned mask = 0;
    for (int i = 0; i < CH2; i++) {
        int v = base + i;
        if (v < NV && g_rank[v]) mask |= (1u << i);
    }
    int cnt = __popc(mask);
    scan[tid] = cnt;
    __syncthreads();
    for (int o = 1; o < 1024; o <<= 1) {
        int add = (tid >= o) ? scan[tid - o] : 0;
        __syncthreads();
        scan[tid] += add;
        __syncthreads();
    }
    int run = scan[tid] - cnt;
    for (int i = 0; i < CH2; i++) {
        int v = base + i;
        if (v < NV) {
            if (mask & (1u << i)) { g_rank[v] = run; g_tokens[run] = v; run++; }
            else g_rank[v] = -1;
        }
    }
    if (tid == 1023) { g_nodeCount = scan[1023] - 1; g_cnt = scan[1023] - 1; }
}

// node features + norms; blocks 0..15 additionally build g_index (both need only k_rank)
__global__ void k_init_nodes(const float* __restrict__ emb, const int* __restrict__ x, int NV) {
    int i = blockIdx.x;
    int e = threadIdx.x;
    int gi = i * 256 + e;
    if (gi < BB * LL) {
        int v = x[gi];
        g_index[gi] = (v == NV - 1) ? -1 : g_rank[v];
    }
    if (i >= g_nodeCount) return;
    float v = emb[(size_t)g_tokens[i] * EE + e];
    g_feats[i * EE + e] = v;
    float s = v * v;
#pragma unroll
    for (int o = 16; o; o >>= 1) s += __shfl_xor_sync(0xffffffffu, s, o);
    __shared__ float red[8];
    if ((e & 31) == 0) red[e >> 5] = s;
    __syncthreads();
    if (e == 0) {
        float t = 0.f;
#pragma unroll
        for (int w = 0; w < 8; w++) t += red[w];
        g_norm[i] = sqrtf(t);
    }
}

__global__ void k_init_cos() {
    int gw = blockIdx.x * 8 + (threadIdx.x >> 5);
    if (gw >= BB * (LL - 1)) return;
    int r = gw / (LL - 1), j = gw % (LL - 1);
    int iR = g_index[r * LL + j + 1];
    float c;
    if (iR < 0) c = NEG_INF;
    else {
        int iL = g_index[r * LL + j];
        float d = warp_dot(&g_feats[iL * EE], &g_feats[iR * EE]);
        c = d / fmaxf(g_norm[iL] * g_norm[iR], 1e-8f);
    }
    if ((threadIdx.x & 31) == 0) g_cos[r * LL + j] = c;
}

// ----------------- async merge tree: 2 CTAs x 32 warps = one warp per row ---------------
// Per-step: prefetch children+neighbor feats BEFORE the hash probe (latency overlap);
// every warp composes nf locally (bitwise-deterministic), so losers never wait on data.
// Norm reads are volatile (L1-bypass): g_norm packs 32 nodes/line, so a plain load
// could hit a stale L1 line for a node created on the other CTA's SM.
__global__ __launch_bounds__(1024) void k_tree(const float* __restrict__ comp_l,
                                               const float* __restrict__ comp_r,
                                               const float* __restrict__ cb) {
    __shared__ int   s_rIdx[32 * 66];
    __shared__ float s_rCos[32 * 64];
    __shared__ int s_len[64], s_base[64];

    int tid = threadIdx.x, lane = tid & 31, w = tid >> 5;
    int cta = blockIdx.x;
    int r = cta * 32 + w;             // this warp's row
    float slv = sigmoidf_(comp_l[lane & 15]);
    float srv = sigmoidf_(comp_r[lane & 15]);
    float cbv = cb[lane & 15];

    // lens for ALL rows (deterministic target bases, computed per-CTA)
    if (tid < 64) {
        int cnt = 0;
        for (int j = 0; j < 64; j++) cnt += (g_index[tid * 64 + j] != -1);
        s_len[tid] = cnt;
    }
    __syncthreads();
    if (tid == 0) {
        int acc = 0;
        for (int q = 0; q < 64; q++) { s_base[q] = acc; acc += 2 * (s_len[q] - 1); }
        if (cta == 0) g_M = acc;
    }
    // load this CTA's 32 rows
    {
        int i0 = g_index[r * 64 + lane];
        int i1 = g_index[r * 64 + lane + 32];
        s_rIdx[w * 66 + lane] = i0;
        s_rIdx[w * 66 + lane + 32] = i1;
        s_rCos[w * 64 + lane] = g_cos[r * 64 + lane];
        if (lane <= 30) s_rCos[w * 64 + lane + 32] = g_cos[r * 64 + lane + 32];
    }
    __syncthreads();

    int* rIdx = &s_rIdx[w * 66];
    float* rCos = &s_rCos[w * 64];
    int L = s_len[r];
    int tb0 = s_base[r];

    for (int v = L; v >= 2; --v) {
        // argmax over rCos[0..v-2], first-index tiebreak
        float c0 = (lane <= v - 2) ? rCos[lane] : NEG_INF;
        float c1 = (lane + 32 <= v - 2) ? rCos[lane + 32] : NEG_INF;
        float bv; int bi;
        if (c0 >= c1) { bv = c0; bi = lane; } else { bv = c1; bi = lane + 32; }
#pragma unroll
        for (int o = 16; o; o >>= 1) {
            float ov = __shfl_xor_sync(0xffffffffu, bv, o);
            int   oi = __shfl_xor_sync(0xffffffffu, bi, o);
            if (ov > bv || (ov == bv && oi < bi)) { bv = ov; bi = oi; }
        }
        int ms = bi;
        int l = rIdx[ms], rr = rIdx[ms + 1];
        bool hasA = (ms >= 1);
        bool hasB = (ms <= v - 3);
        int a = hasA ? rIdx[ms - 1] : 0;
        int b = hasB ? rIdx[ms + 2] : 0;   // post-shift right neighbor of the new node
        unsigned key = ((unsigned)l << 13) | (unsigned)rr;

        // ---- issue ALL feature loads BEFORE the probe (overlap latencies) ----
        const float* FL = &g_feats[(size_t)l * EE];
        const float* FR = &g_feats[(size_t)rr * EE];
        const float* FA = &g_feats[(size_t)a * EE];
        const float* FB = &g_feats[(size_t)b * EE];
        float fl[8], fr[8], fa[8], fb[8];
#pragma unroll
        for (int k = 0; k < 8; k++) {
            fl[k] = FL[lane + 32 * k];
            fr[k] = FR[lane + 32 * k];
            fa[k] = FA[lane + 32 * k];
            fb[k] = FB[lane + 32 * k];
        }
        float na_ = *(volatile float*)&g_norm[a];
        float nb_ = *(volatile float*)&g_norm[b];

        // ---- dedup via GLOBAL hash: lane 0 probes/claims (loads still in flight) ----
        int nid = -1, claim = 0; unsigned hh = 0;
        if (lane == 0) {
            unsigned h = (key * 2654435761u) & (HASHSZ - 1);
            for (int p = 0; p < HASHSZ; p++) {
                int old = atomicCAS(&g_hkey[h], -1, (int)key);
                if (old == -1) {
                    claim = 1;
                    nid = atomicAdd(&g_cnt, 1);
                    if (nid >= MAXN) nid = MAXN - 1;  // fail-soft
                    hh = h;
                    break;
                }
                if ((unsigned)old == key) {
                    volatile int* vp = &g_hval[h];
                    int x, t = 0;
                    while ((x = *vp) < 0 && ++t < (1 << 20)) {}
                    nid = (x < 0) ? 0 : x;  // fail-soft
                    break;
                }
                h = (h + 1) & (HASHSZ - 1);
            }
            if (nid < 0) nid = 0;  // fail-soft
        }
        nid   = __shfl_sync(0xffffffffu, nid, 0);
        claim = __shfl_sync(0xffffffffu, claim, 0);
        hh    = __shfl_sync(0xffffffffu, hh, 0);

        // ---- EVERY warp composes locally: bitwise-deterministic, no data wait ----
        float nf[8]; float ss = 0.f;
#pragma unroll
        for (int k = 0; k < 8; k++) {
            float x = fl[k] * slv + fr[k] * srv + cbv;
            nf[k] = x;
            ss += x * x;
        }
#pragma unroll
        for (int o = 16; o; o >>= 1) ss += __shfl_xor_sync(0xffffffffu, ss, o);
        float nn = sqrtf(ss);

        if (claim) {
#pragma unroll
            for (int k = 0; k < 8; k++) g_feats[(size_t)nid * EE + lane + 32 * k] = nf[k];
            if (lane == 0) g_norm[nid] = nn;
            __threadfence();                                   // data visible before publish
            if (lane == 0) *(volatile int*)&g_hval[hh] = nid;  // publish
        }

        // record targets at deterministic per-row offset
        if (lane == 0) {
            int ls = hasA ? a : -1;
            int rs = (ms + 2 >= v) ? ((L == 64) ? -2 : -1) : rIdx[ms + 2];
            int tb = tb0 + 2 * (L - v);
            g_targets[tb * 3 + 0] = l;  g_targets[tb * 3 + 1] = ls; g_targets[tb * 3 + 2] = rr;
            g_targets[tb * 3 + 3] = rr; g_targets[tb * 3 + 4] = l;  g_targets[tb * 3 + 5] = rs;
        }

        // shift arrays left past ms (read-before-write within warp)
        int j0 = lane, j1 = lane + 32;
        int ni0 = 0, ni1 = 0; float nc0 = 0.f, nc1 = 0.f;
        if (j0 <= v - 2) ni0 = (j0 == ms) ? nid : rIdx[j0 + (j0 > ms)];
        if (j1 <= v - 2) ni1 = (j1 == ms) ? nid : rIdx[j1 + (j1 > ms)];
        if (j0 <= v - 3) nc0 = (j0 < ms - 1) ? rCos[j0] : ((j0 > ms) ? rCos[j0 + 1] : 0.f);
        if (j1 <= v - 3) nc1 = (j1 < ms - 1) ? rCos[j1] : ((j1 > ms) ? rCos[j1 + 1] : 0.f);
        __syncwarp();
        if (j0 <= v - 2) rIdx[j0] = ni0;
        if (j1 <= v - 2) rIdx[j1] = ni1;
        if (j0 <= v - 3) rCos[j0] = nc0;
        if (j1 <= v - 3) rCos[j1] = nc1;
        __syncwarp();

        // recompute the <=2 affected cosines from prefetched registers (no reloads)
        if (hasA) {
            float s = 0.f;
#pragma unroll
            for (int k = 0; k < 8; k++) s += nf[k] * fa[k];
#pragma unroll
            for (int o = 16; o; o >>= 1) s += __shfl_xor_sync(0xffffffffu, s, o);
            float c = s / fmaxf(na_ * nn, 1e-8f);
            if (lane == 0) rCos[ms - 1] = c;
        }
        if (hasB) {
            float s = 0.f;
#pragma unroll
            for (int k = 0; k < 8; k++) s += nf[k] * fb[k];
#pragma unroll
            for (int o = 16; o; o >>= 1) s += __shfl_xor_sync(0xffffffffu, s, o);
            float c = s / fmaxf(nn * nb_, 1e-8f);
            if (lane == 0) rCos[ms] = c;
        }
        __syncwarp();
    }
}

// append eos (N-2) and sos (N-1); finalize node count from global counter
__global__ void k_finalize(const float* __restrict__ sos, const float* __restrict__ eos) {
    int nc = g_cnt;
    int e = threadIdx.x;
    if (blockIdx.x == 0) {
        g_feats[nc * EE + e] = eos[e];
        if (e == 0) g_nodeCount = nc;
    } else {
        g_feats[(nc + 1) * EE + e] = sos[e];
    }
}

// compose contexts + A-split; also converts feats row m to B-split (fused k_cvtB)
__global__ void k_outs(const float* __restrict__ comp_l, const float* __restrict__ comp_r,
                       const float* __restrict__ cb) {
    int m = blockIdx.x;
    int e = threadIdx.x;
    {   // B split for feats row m (all MAXN rows)
        float v = g_feats[(size_t)m * EE + e];
        __half h = __float2half_rn(v);
        g_Bhi[(size_t)m * EE + e] = h;
        g_Blo[(size_t)m * EE + e] = __float2half_rn(v - __half2float(h));
    }
    if (m >= g_M) return;
    int N = g_nodeCount + 2;
    int t1 = g_targets[m * 3 + 1]; if (t1 < 0) t1 += N;
    int t2 = g_targets[m * 3 + 2]; if (t2 < 0) t2 += N;
    int c = e & 15;
    float sl = sigmoidf_(comp_l[c]), sr = sigmoidf_(comp_r[c]);
    float o = g_feats[t1 * EE + e] * sl + g_feats[t2 * EE + e] * sr + cb[c];
    g_outs[m * EE + e] = o;
    __half h = __float2half_rn(o);
    g_Ahi[m * EE + e] = h;
    g_Alo[m * EE + e] = __float2half_rn(o - __half2float(h));
}

// ----------------- mma.sync GEMM: A-fragment register reuse, 2 CTAs/SM -----------------
__device__ __forceinline__ uint32_t smem_u32(const void* p) {
    uint32_t a;
    asm("{ .reg .u64 t; cvta.to.shared.u64 t, %1; cvt.u32.u64 %0, t; }" : "=r"(a) : "l"(p));
    return a;
}
__device__ __forceinline__ void ldsm_x4(uint32_t* r, uint32_t addr) {
    asm volatile("ldmatrix.sync.aligned.m8n8.x4.shared.b16 {%0,%1,%2,%3}, [%4];"
                 : "=r"(r[0]), "=r"(r[1]), "=r"(r[2]), "=r"(r[3]) : "r"(addr));
}
__device__ __forceinline__ void ldsm_x2(uint32_t* r, uint32_t addr) {
    asm volatile("ldmatrix.sync.aligned.m8n8.x2.shared.b16 {%0,%1}, [%2];"
                 : "=r"(r[0]), "=r"(r[1]) : "r"(addr));
}
__device__ __forceinline__ void mma16816(float* c, const uint32_t* a, const uint32_t* b) {
    asm volatile(
        "mma.sync.aligned.m16n8k16.row.col.f32.f16.f16.f32 "
        "{%0,%1,%2,%3}, {%4,%5,%6,%7}, {%8,%9}, {%0,%1,%2,%3};"
        : "+f"(c[0]), "+f"(c[1]), "+f"(c[2]), "+f"(c[3])
        : "r"(a[0]), "r"(a[1]), "r"(a[2]), "r"(a[3]), "r"(b[0]), "r"(b[1]));
}

#define SROW 40  // smem row stride in halves (conflict-free ldmatrix)

__global__ __launch_bounds__(256, 2) void k_gemm_mma() {
    __shared__ __half sAhi[128 * SROW], sAlo[128 * SROW];
    __shared__ __half sBhi[128 * SROW], sBlo[128 * SROW];
    int M = g_M, N = g_nodeCount + 2;
    int m0 = blockIdx.y * 128, n0 = blockIdx.x * 128;
    if (m0 >= M || n0 >= N) return;

    int tid = threadIdx.x, lane = tid & 31, warp = tid >> 5;
    int wm = warp >> 2, wn = warp & 3;

    float c[4][4][4];
#pragma unroll
    for (int i = 0; i < 4; i++)
#pragma unroll
        for (int j = 0; j < 4; j++)
#pragma unroll
            for (int r = 0; r < 4; r++) c[i][j][r] = 0.f;

    uint32_t aBase = smem_u32(sAhi), alBase = smem_u32(sAlo);
    uint32_t bBase = smem_u32(sBhi), blBase = smem_u32(sBlo);

    int aRow = wm * 64 + (lane & 15);
    int aCol = 8 * (lane >> 4);
    int l16 = lane & 15;
    int bCol = 8 * (l16 >> 3);

    for (int kc = 0; kc < 8; kc++) {
        __syncthreads();
#pragma unroll
        for (int s = 0; s < 2; s++) {
            int id = tid + s * 256;
            int row = id >> 2, kg = id & 3;
            size_t goff = (size_t)row * EE + kc * 32 + kg * 8;
            int soff = row * SROW + kg * 8;
            *(uint4*)&sAhi[soff] = *(const uint4*)&g_Ahi[(size_t)m0 * EE + goff];
            *(uint4*)&sAlo[soff] = *(const uint4*)&g_Alo[(size_t)m0 * EE + goff];
            *(uint4*)&sBhi[soff] = *(const uint4*)&g_Bhi[(size_t)n0 * EE + goff];
            *(uint4*)&sBlo[soff] = *(const uint4*)&g_Blo[(size_t)n0 * EE + goff];
        }
        __syncthreads();

#pragma unroll
        for (int k16 = 0; k16 < 2; k16++) {
            int kb = k16 * 16;
            uint32_t a[4][4], bhi[4][2], tmp[4][2];
            // pass 1: a = Ahi, acc += Ahi*Bhi
#pragma unroll
            for (int mt = 0; mt < 4; mt++)
                ldsm_x4(a[mt], aBase + ((aRow + mt * 16) * SROW + kb + aCol) * 2);
#pragma unroll
            for (int nt = 0; nt < 4; nt++)
                ldsm_x2(bhi[nt], bBase + ((wn * 32 + nt * 8 + (l16 & 7)) * SROW + kb + bCol) * 2);
#pragma unroll
            for (int mt = 0; mt < 4; mt++)
#pragma unroll
                for (int nt = 0; nt < 4; nt++) mma16816(c[mt][nt], a[mt], bhi[nt]);
            // pass 2: acc += Ahi*Blo
#pragma unroll
            for (int nt = 0; nt < 4; nt++)
                ldsm_x2(tmp[nt], blBase + ((wn * 32 + nt * 8 + (l16 & 7)) * SROW + kb + bCol) * 2);
#pragma unroll
            for (int mt = 0; mt < 4; mt++)
#pragma unroll
                for (int nt = 0; nt < 4; nt++) mma16816(c[mt][nt], a[mt], tmp[nt]);
            // pass 3: a = Alo (register reuse), acc += Alo*Bhi
#pragma unroll
            for (int mt = 0; mt < 4; mt++)
                ldsm_x4(a[mt], alBase + ((aRow + mt * 16) * SROW + kb + aCol) * 2);
#pragma unroll
            for (int mt = 0; mt < 4; mt++)
#pragma unroll
                for (int nt = 0; nt < 4; nt++) mma16816(c[mt][nt], a[mt], bhi[nt]);
        }
    }

#pragma unroll
    for (int mt = 0; mt < 4; mt++) {
#pragma unroll
        for (int nt = 0; nt < 4; nt++) {
            int m = m0 + wm * 64 + mt * 16 + (lane >> 2);
            int n = n0 + wn * 32 + nt * 8 + 2 * (lane & 3);
            *(float2*)&g_logits[(size_t)m * MAXN + n] = make_float2(c[mt][nt][0], c[mt][nt][1]);
            *(float2*)&g_logits[(size_t)(m + 8) * MAXN + n] = make_float2(c[mt][nt][2], c[mt][nt][3]);
        }
    }
}

__global__ __launch_bounds__(256) void k_lse() {
    int m = blockIdx.x;
    if (m >= g_M) return;
    int N = g_nodeCount + 2;
    const float* row = &g_logits[(size_t)m * MAXN];
    const float4* row4 = (const float4*)row;
    int N4 = N >> 2;
    int tid = threadIdx.x;
    __shared__ float sh[256];
    float mx = NEG_INF;
    for (int j = tid; j < N4; j += 256) {
        float4 v = row4[j];
        mx = fmaxf(mx, fmaxf(fmaxf(v.x, v.y), fmaxf(v.z, v.w)));
    }
    for (int j = 4 * N4 + tid; j < N; j += 256) mx = fmaxf(mx, row[j]);
    sh[tid] = mx; __syncthreads();
    for (int o = 128; o; o >>= 1) { if (tid < o) sh[tid] = fmaxf(sh[tid], sh[tid + o]); __syncthreads(); }
    mx = sh[0]; __syncthreads();
    float se = 0.f;
    for (int j = tid; j < N4; j += 256) {
        float4 v = row4[j];
        se += expf(v.x - mx) + expf(v.y - mx) + expf(v.z - mx) + expf(v.w - mx);
    }
    for (int j = 4 * N4 + tid; j < N; j += 256) se += expf(row[j] - mx);
    sh[tid] = se; __syncthreads();
    for (int o = 128; o; o >>= 1) { if (tid < o) sh[tid] += sh[tid + o]; __syncthreads(); }
    if (tid == 0) {
        int t0 = g_targets[m * 3];
        g_rowloss[m] = mx + logf(sh[0]) - row[t0];
    }
}

__global__ __launch_bounds__(1024) void k_reduce(float* __restrict__ out) {
    __shared__ float sh[1024];
    int M = g_M;
    float s = 0.f;
    for (int i = threadIdx.x; i < M; i += 1024) s += g_rowloss[i];
    sh[threadIdx.x] = s; __syncthreads();
    for (int o = 512; o; o >>= 1) { if (threadIdx.x < o) sh[threadIdx.x] += sh[threadIdx.x + o]; __syncthreads(); }
    if (threadIdx.x == 0) out[0] = sh[0] / (float)M;
}

// ----------------- launcher -----------------
extern "C" void kernel_launch(void* const* d_in, const int* in_sizes, int n_in,
                              void* d_out, int out_size) {
    const int*   x      = (const int*)  d_in[0];
    const float* emb    = (const float*)d_in[1];
    const float* comp_l = (const float*)d_in[2];
    const float* comp_r = (const float*)d_in[3];
    const float* cb     = (const float*)d_in[4];
    const float* sos    = (const float*)d_in[5];
    const float* eos    = (const float*)d_in[6];
    int NV = in_sizes[1] / EE;  // vocab size (pad token = NV-1)

    k_zero<<<121, 256>>>();
    k_mark<<<16, 256>>>(x);
    k_rank<<<1, 1024>>>(NV);
    k_init_nodes<<<4096, 256>>>(emb, x, NV);
    k_init_cos<<<504, 256>>>();
    k_tree<<<2, 1024>>>(comp_l, comp_r, cb);
    k_finalize<<<2, 256>>>(sos, eos);
    k_outs<<<MAXM, 256>>>(comp_l, comp_r, cb);
    k_gemm_mma<<<dim3(64, 64), 256>>>();
    k_lse<<<MAXM, 256>>>();
    k_reduce<<<1, 1024>>>((float*)d_out);
}